// round 2
// baseline (speedup 1.0000x reference)
#include <cuda_runtime.h>
#include <math.h>

// Problem constants
#define B_    512
#define NS    128
#define IN_   2048
#define MEM_  64
#define OUT_  2048
#define RCOLS 65          // MEM_+1 columns of W_r
#define KO    2176        // IN_ + 2*MEM_ (W_o rows)
#define NPAD  132         // packed projection width (64 q | 1 f | 65 r | 2 pad)

// ------------------------------------------------------------------
// Scratch (device globals; harness forbids allocation)
// ------------------------------------------------------------------
__device__ float g_q  [B_ * MEM_];    // x @ W_ar + b_ar
__device__ float g_xf [B_];           // x @ W_f[:IN] + b_f
__device__ float g_xr [B_ * RCOLS];   // x @ W_r[:IN] + b_r
__device__ float g_act[B_ * MEM_];    // active recall
__device__ float g_pas[B_ * MEM_];    // passive recall
__device__ float g_W  [IN_ * NPAD];   // packed [k][col] projection weights

// ==================================================================
// Kernel P: pack W_ar | W_f | W_r into g_W[k][col], pitch NPAD.
// ==================================================================
__global__ __launch_bounds__(256) void pack_kernel(
    const float* __restrict__ W_ar,
    const float* __restrict__ W_f,
    const float* __restrict__ W_r)
{
    int idx = blockIdx.x * 256 + threadIdx.x;
    if (idx >= IN_ * NPAD) return;
    int k = idx / NPAD, c = idx - k * NPAD;
    float v = 0.f;
    if (c < 64)       v = W_ar[(size_t)k * 64 + c];
    else if (c == 64) v = W_f[k];
    else if (c < 130) v = W_r[(size_t)k * RCOLS + (c - 65)];
    g_W[idx] = v;
}

// ==================================================================
// Kernel A: fused projections, k-split for full occupancy.
// grid = 128 (GROUP=4 batch rows/block), blockDim = 544 (17 warps).
// Thread layout: col = t % 136 (130 live cols), kq = t / 136 (4 k-slices
// of 512 each). Partials reduced through SMEM.
// ==================================================================
#define GROUP    4
#define PTHREADS 544
#define KQ       4
#define CW       136
__global__ __launch_bounds__(PTHREADS) void proj_kernel(
    const float* __restrict__ x,
    const float* __restrict__ b_ar,
    const float* __restrict__ b_f,
    const float* __restrict__ b_r)
{
    __shared__ float xs[GROUP][IN_];            // 32 KB
    __shared__ float red[GROUP][KQ][CW];        // 8.7 KB

    const int b0 = blockIdx.x * GROUP;

    for (int i = threadIdx.x; i < GROUP * (IN_ / 4); i += PTHREADS) {
        int g = i >> 9, k4 = i & 511;
        ((float4*)xs[g])[k4] = ((const float4*)(x + (size_t)(b0 + g) * IN_))[k4];
    }
    __syncthreads();

    const int t   = threadIdx.x;
    const int col = t % CW;
    const int kq  = t / CW;

    float acc[GROUP] = {0.f, 0.f, 0.f, 0.f};
    if (col < NPAD) {
        const int kbase = kq * (IN_ / KQ);
        const float* wp = g_W + (size_t)kbase * NPAD + col;
        #pragma unroll 8
        for (int k = 0; k < IN_ / KQ; k++) {
            float w = wp[(size_t)k * NPAD];
            int kk = kbase + k;
            acc[0] = fmaf(xs[0][kk], w, acc[0]);
            acc[1] = fmaf(xs[1][kk], w, acc[1]);
            acc[2] = fmaf(xs[2][kk], w, acc[2]);
            acc[3] = fmaf(xs[3][kk], w, acc[3]);
        }
    }
    #pragma unroll
    for (int g = 0; g < GROUP; g++) red[g][kq][col] = acc[g];
    __syncthreads();

    if (kq == 0 && col < 130) {
        float bias = (col < 64) ? b_ar[col] : (col == 64 ? b_f[0] : b_r[col - 65]);
        #pragma unroll
        for (int g = 0; g < GROUP; g++) {
            float s = red[g][0][col] + red[g][1][col] + red[g][2][col] + red[g][3][col] + bias;
            int b = b0 + g;
            if (col < 64)       g_q[(size_t)b * MEM_ + col] = s;
            else if (col == 64) g_xf[b] = s;
            else                g_xr[(size_t)b * RCOLS + (col - 65)] = s;
        }
    }
}

// ==================================================================
// Kernel B: everything that touches `memory`, fused. (unchanged)
// ==================================================================
__device__ __forceinline__ float blockReduce256(float v, float* red8, int isSum)
{
    #pragma unroll
    for (int o = 16; o; o >>= 1) {
        float u = __shfl_xor_sync(0xffffffffu, v, o);
        v = isSum ? (v + u) : fmaxf(v, u);
    }
    if ((threadIdx.x & 31) == 0) red8[threadIdx.x >> 5] = v;
    __syncthreads();
    float r = red8[0];
    #pragma unroll
    for (int i = 1; i < 8; i++) r = isSum ? (r + red8[i]) : fmaxf(r, red8[i]);
    __syncthreads();
    return r;
}

__global__ __launch_bounds__(256) void mem_kernel(
    const float* __restrict__ memory,
    const float* __restrict__ W_pr, const float* __restrict__ b_pr,
    const float* __restrict__ W_f,
    const float* __restrict__ W_r,
    float* __restrict__ new_memory)
{
    extern __shared__ float sm[];
    float* ms   = sm;               // 128*65 = 8320
    float* ws   = ms  + 8320;       // 64*66  = 4224
    float* rem  = ws  + 4224;       // 128*66 = 8448
    float* qs   = rem + 8448;       // 64
    float* wpr  = qs  + 64;         // 64
    float* xrs  = wpr + 64;         // 66
    float* s1   = xrs + 66;         // 128
    float* s2   = s1  + 128;        // 128
    float* red8 = s2  + 128;        // 8

    const int b = blockIdx.x;
    const int t = threadIdx.x;
    const float* memb = memory + (size_t)b * NS * MEM_;

    for (int i = t; i < NS * MEM_; i += 256) {
        int n = i >> 6, m = i & 63;
        ms[n * 65 + m] = memb[i];
    }
    for (int i = t; i < 64 * 66; i += 256) {
        int k = i / 66, j = i - k * 66;
        ws[i] = (j < 65) ? W_r[(size_t)(IN_ + k) * RCOLS + j] : W_f[IN_ + k];
    }
    if (t < 64)  { qs[t] = g_q[(size_t)b * MEM_ + t]; wpr[t] = W_pr[t]; }
    if (t < 65)  { xrs[t] = g_xr[(size_t)b * RCOLS + t]; }
    __syncthreads();

    float s1v = -1e30f, s2v = -1e30f;
    if (t < NS) {
        float a = 0.f, p = 0.f;
        #pragma unroll 8
        for (int k = 0; k < MEM_; k++) {
            float mv = ms[t * 65 + k];
            a = fmaf(mv, qs[k], a);
            p = fmaf(mv, wpr[k], p);
        }
        s1v = a;
        s2v = p + b_pr[0];
    }
    float max1 = blockReduce256(s1v, red8, 0);
    float max2 = blockReduce256(s2v, red8, 0);
    float e1 = (t < NS) ? expf(s1v - max1) : 0.f;
    float e2 = (t < NS) ? expf(s2v - max2) : 0.f;
    float sum1 = blockReduce256(e1, red8, 1);
    float sum2 = blockReduce256(e2, red8, 1);
    if (t < NS) { s1[t] = e1 / sum1; s2[t] = e2 / sum2; }
    __syncthreads();

    if (t < MEM_) {
        float act = 0.f, pas = 0.f;
        #pragma unroll 4
        for (int n = 0; n < NS; n++) {
            float mv = ms[n * 65 + t];
            act = fmaf(s1[n], mv, act);
            pas = fmaf(s2[n], mv, pas);
        }
        g_act[(size_t)b * MEM_ + t] = act;
        g_pas[(size_t)b * MEM_ + t] = pas;
    }

    if (t < 132) {
        const int j   = t % 66;
        const int nlo = (t / 66) * 64;
        float w[64];
        #pragma unroll
        for (int k = 0; k < 64; k++) w[k] = ws[k * 66 + j];
        const float base = (j < 65) ? xrs[j] : g_xf[b];
        #pragma unroll 2
        for (int n = nlo; n < nlo + 64; n++) {
            float acc = base;
            #pragma unroll
            for (int k = 0; k < 64; k++)
                acc = fmaf(ms[n * 65 + k], w[k], acc);
            if (j < 65) rem[n * 66 + j] = acc;
            else        rem[n * 66 + 65] = 1.1f / (1.f + expf(-acc));
        }
    }
    __syncthreads();

    float* nm = new_memory + (size_t)b * NS * MEM_;
    for (int i = t; i < NS * MEM_; i += 256) {
        int n = i >> 6, m = i & 63;
        float f    = rem[n * 66 + 65];
        float gate = rem[n * 66 + 64];
        nm[i] = fmaf(ms[n * 65 + m], f, gate * rem[n * 66 + m]);
    }
}

// ==================================================================
// Kernel C: output = [x | active | passive] @ W_o + b_o
// [512,2176] x [2176,2048]. Tile 128x64x16, 8x4 microtile, 256 thr.
// ==================================================================
__global__ __launch_bounds__(256) void out_gemm(
    const float* __restrict__ x,
    const float* __restrict__ W_o, const float* __restrict__ b_o,
    float* __restrict__ out)
{
    __shared__ float As[16 * 136];  // [kk][row], pitch 136 (16B-aligned rows)
    __shared__ float Bs[16 * 64];   // [kk][col]

    const int br = blockIdx.y * 128;
    const int bc = blockIdx.x * 64;
    const int t  = threadIdx.x;
    const int tx = t & 15;          // col group (4 cols)
    const int ty = t >> 4;          // row group (8 rows)

    float acc[8][4];
    #pragma unroll
    for (int i = 0; i < 8; i++)
        #pragma unroll
        for (int j = 0; j < 4; j++) acc[i][j] = 0.f;

    for (int k0 = 0; k0 < KO; k0 += 16) {
        // A tile: 128 rows x 16 k
        {
            int kk = t & 15;
            int r0 = t >> 4;
            int gk = k0 + kk;
            #pragma unroll
            for (int p = 0; p < 8; p++) {
                int row = r0 + p * 16;
                int gb  = br + row;
                float v;
                if (gk < IN_)            v = x[(size_t)gb * IN_ + gk];
                else if (gk < IN_ + 64)  v = g_act[(size_t)gb * MEM_ + (gk - IN_)];
                else                     v = g_pas[(size_t)gb * MEM_ + (gk - IN_ - 64)];
                As[kk * 136 + row] = v;
            }
        }
        // B tile: 16 k x 64 cols
        {
            int nn  = t & 63;
            int kk0 = t >> 6;
            #pragma unroll
            for (int p = 0; p < 4; p++) {
                int kk = kk0 + p * 4;
                Bs[kk * 64 + nn] = W_o[(size_t)(k0 + kk) * OUT_ + bc + nn];
            }
        }
        __syncthreads();

        #pragma unroll
        for (int kk = 0; kk < 16; kk++) {
            float4 a0 = *(const float4*)&As[kk * 136 + ty * 8];
            float4 a1 = *(const float4*)&As[kk * 136 + ty * 8 + 4];
            float4 bv = *(const float4*)&Bs[kk * 64 + tx * 4];
            acc[0][0] = fmaf(a0.x, bv.x, acc[0][0]); acc[0][1] = fmaf(a0.x, bv.y, acc[0][1]);
            acc[0][2] = fmaf(a0.x, bv.z, acc[0][2]); acc[0][3] = fmaf(a0.x, bv.w, acc[0][3]);
            acc[1][0] = fmaf(a0.y, bv.x, acc[1][0]); acc[1][1] = fmaf(a0.y, bv.y, acc[1][1]);
            acc[1][2] = fmaf(a0.y, bv.z, acc[1][2]); acc[1][3] = fmaf(a0.y, bv.w, acc[1][3]);
            acc[2][0] = fmaf(a0.z, bv.x, acc[2][0]); acc[2][1] = fmaf(a0.z, bv.y, acc[2][1]);
            acc[2][2] = fmaf(a0.z, bv.z, acc[2][2]); acc[2][3] = fmaf(a0.z, bv.w, acc[2][3]);
            acc[3][0] = fmaf(a0.w, bv.x, acc[3][0]); acc[3][1] = fmaf(a0.w, bv.y, acc[3][1]);
            acc[3][2] = fmaf(a0.w, bv.z, acc[3][2]); acc[3][3] = fmaf(a0.w, bv.w, acc[3][3]);
            acc[4][0] = fmaf(a1.x, bv.x, acc[4][0]); acc[4][1] = fmaf(a1.x, bv.y, acc[4][1]);
            acc[4][2] = fmaf(a1.x, bv.z, acc[4][2]); acc[4][3] = fmaf(a1.x, bv.w, acc[4][3]);
            acc[5][0] = fmaf(a1.y, bv.x, acc[5][0]); acc[5][1] = fmaf(a1.y, bv.y, acc[5][1]);
            acc[5][2] = fmaf(a1.y, bv.z, acc[5][2]); acc[5][3] = fmaf(a1.y, bv.w, acc[5][3]);
            acc[6][0] = fmaf(a1.z, bv.x, acc[6][0]); acc[6][1] = fmaf(a1.z, bv.y, acc[6][1]);
            acc[6][2] = fmaf(a1.z, bv.z, acc[6][2]); acc[6][3] = fmaf(a1.z, bv.w, acc[6][3]);
            acc[7][0] = fmaf(a1.w, bv.x, acc[7][0]); acc[7][1] = fmaf(a1.w, bv.y, acc[7][1]);
            acc[7][2] = fmaf(a1.w, bv.z, acc[7][2]); acc[7][3] = fmaf(a1.w, bv.w, acc[7][3]);
        }
        __syncthreads();
    }

    const float4 bb = *(const float4*)&b_o[bc + tx * 4];
    #pragma unroll
    for (int i = 0; i < 8; i++) {
        int row = br + ty * 8 + i;
        float4 v = make_float4(acc[i][0] + bb.x, acc[i][1] + bb.y,
                               acc[i][2] + bb.z, acc[i][3] + bb.w);
        *(float4*)&out[(size_t)row * OUT_ + bc + tx * 4] = v;
    }
}

// ==================================================================
// Launch
// ==================================================================
extern "C" void kernel_launch(void* const* d_in, const int* in_sizes, int n_in,
                              void* d_out, int out_size)
{
    const float* x    = (const float*)d_in[0];
    const float* mem  = (const float*)d_in[1];
    const float* W_ar = (const float*)d_in[2];
    const float* b_ar = (const float*)d_in[3];
    const float* W_pr = (const float*)d_in[4];
    const float* b_pr = (const float*)d_in[5];
    const float* W_f  = (const float*)d_in[6];
    const float* b_f  = (const float*)d_in[7];
    const float* W_r  = (const float*)d_in[8];
    const float* b_r  = (const float*)d_in[9];
    const float* W_o  = (const float*)d_in[10];
    const float* b_o  = (const float*)d_in[11];

    float* out     = (float*)d_out;                     // [512, 2048]
    float* new_mem = out + (size_t)B_ * OUT_;           // [512, 128, 64]

    // Pack projection weights
    pack_kernel<<<(IN_ * NPAD + 255) / 256, 256>>>(W_ar, W_f, W_r);

    // Projections of x
    proj_kernel<<<B_ / GROUP, PTHREADS>>>(x, b_ar, b_f, b_r);

    // Memory-fused (recalls + gated update)
    static bool attr_done = false;
    const int smemB = (8320 + 4224 + 8448 + 64 + 64 + 66 + 128 + 128 + 8) * 4;
    if (!attr_done) {
        cudaFuncSetAttribute(mem_kernel,
                             cudaFuncAttributeMaxDynamicSharedMemorySize, smemB);
        attr_done = true;
    }
    mem_kernel<<<B_, 256, smemB>>>(mem, W_pr, b_pr, W_f, W_r, new_mem);

    // Output GEMM
    dim3 gridC(OUT_ / 64, B_ / 128);
    out_gemm<<<gridC, 256>>>(x, W_o, b_o, out);
}

// round 4
// speedup vs baseline: 1.8938x; 1.8938x over previous
#include <cuda_runtime.h>
#include <cuda_bf16.h>
#include <math.h>
#include <cstdint>

// Problem constants
#define B_    512
#define NS    128
#define IN_   2048
#define MEM_  64
#define OUT_  2048
#define RCOLS 65
#define KO    2176          // IN_ + 2*MEM_
#define NPAD  132

// ------------------------------------------------------------------
// Scratch (device globals)
// ------------------------------------------------------------------
__device__ float g_q  [B_ * MEM_];
__device__ float g_xf [B_];
__device__ float g_xr [B_ * RCOLS];
__device__ float g_W  [IN_ * NPAD];
__device__ __nv_bfloat16 g_Ahi[B_ * KO];       // [512][2176]  (x | act | pas)
__device__ __nv_bfloat16 g_Alo[B_ * KO];
__device__ __nv_bfloat16 g_Bhi[OUT_ * KO];     // [2048][2176] = W_o^T
__device__ __nv_bfloat16 g_Blo[OUT_ * KO];

// ------------------------------------------------------------------
// Helpers
// ------------------------------------------------------------------
__device__ __forceinline__ uint32_t smem_u32(const void* p) {
    uint32_t a;
    asm("{ .reg .u64 t; cvta.to.shared.u64 t, %1; cvt.u32.u64 %0, t; }"
        : "=r"(a) : "l"(p));
    return a;
}
__device__ __forceinline__ void cp16(uint32_t dst, const void* src) {
    asm volatile("cp.async.cg.shared.global [%0], [%1], 16;" :: "r"(dst), "l"(src));
}
#define CP_COMMIT()  asm volatile("cp.async.commit_group;" ::: "memory")
#define CP_WAIT(n)   asm volatile("cp.async.wait_group %0;" :: "n"(n) : "memory")

__device__ __forceinline__ void ldm_x4(uint32_t* r, uint32_t addr) {
    asm volatile("ldmatrix.sync.aligned.m8n8.x4.shared.b16 {%0,%1,%2,%3}, [%4];"
        : "=r"(r[0]), "=r"(r[1]), "=r"(r[2]), "=r"(r[3]) : "r"(addr));
}
__device__ __forceinline__ void mma16816(float* c, const uint32_t* a, const uint32_t* b) {
    asm volatile(
        "mma.sync.aligned.m16n8k16.row.col.f32.bf16.bf16.f32 "
        "{%0,%1,%2,%3}, {%4,%5,%6,%7}, {%8,%9}, {%0,%1,%2,%3};"
        : "+f"(c[0]), "+f"(c[1]), "+f"(c[2]), "+f"(c[3])
        : "r"(a[0]), "r"(a[1]), "r"(a[2]), "r"(a[3]), "r"(b[0]), "r"(b[1]));
}
__device__ __forceinline__ void split_bf16(float v, __nv_bfloat16& h, __nv_bfloat16& l) {
    h = __float2bfloat16(v);
    l = __float2bfloat16(v - __bfloat162float(h));
}

// ==================================================================
// Prep kernels
// ==================================================================
__global__ __launch_bounds__(256) void pack_kernel(
    const float* __restrict__ W_ar, const float* __restrict__ W_f,
    const float* __restrict__ W_r)
{
    int idx = blockIdx.x * 256 + threadIdx.x;
    if (idx >= IN_ * NPAD) return;
    int k = idx / NPAD, c = idx - k * NPAD;
    float v = 0.f;
    if (c < 64)       v = W_ar[(size_t)k * 64 + c];
    else if (c == 64) v = W_f[k];
    else if (c < 130) v = W_r[(size_t)k * RCOLS + (c - 65)];
    g_W[idx] = v;
}

// x -> bf16 hi/lo into g_A*(cols 0..2047)
__global__ __launch_bounds__(256) void conv_x_kernel(const float* __restrict__ x)
{
    int i8 = blockIdx.x * 256 + threadIdx.x;       // 512*2048/8 = 131072
    int row = i8 >> 8;
    int col = (i8 & 255) * 8;
    const float4 v0 = *(const float4*)(x + (size_t)row * IN_ + col);
    const float4 v1 = *(const float4*)(x + (size_t)row * IN_ + col + 4);
    __nv_bfloat16 h[8], l[8];
    const float vv[8] = {v0.x, v0.y, v0.z, v0.w, v1.x, v1.y, v1.z, v1.w};
    #pragma unroll
    for (int j = 0; j < 8; j++) split_bf16(vv[j], h[j], l[j]);
    *(uint4*)(g_Ahi + (size_t)row * KO + col) = *(const uint4*)h;
    *(uint4*)(g_Alo + (size_t)row * KO + col) = *(const uint4*)l;
}

// W_o [K=2176][N=2048] -> g_B* [N][K] bf16 hi/lo (tiled transpose)
__global__ __launch_bounds__(256) void conv_B_kernel(const float* __restrict__ W_o)
{
    __shared__ float t[32][33];
    const int k0 = blockIdx.x * 32;
    const int n0 = blockIdx.y * 32;
    const int tid = threadIdx.x;
    #pragma unroll
    for (int p = 0; p < 4; p++) {
        int r = (tid >> 5) + p * 8, c = tid & 31;
        t[r][c] = W_o[(size_t)(k0 + r) * OUT_ + n0 + c];
    }
    __syncthreads();
    #pragma unroll
    for (int p = 0; p < 2; p++) {
        int r = (tid >> 4) + p * 16;           // n within tile
        int cc = (tid & 15) * 2;               // k pair
        float v0 = t[cc][r], v1 = t[cc + 1][r];
        __nv_bfloat16 h0, l0, h1, l1;
        split_bf16(v0, h0, l0);
        split_bf16(v1, h1, l1);
        __nv_bfloat162 hp; hp.x = h0; hp.y = h1;
        __nv_bfloat162 lp; lp.x = l0; lp.y = l1;
        *(__nv_bfloat162*)(g_Bhi + (size_t)(n0 + r) * KO + k0 + cc) = hp;
        *(__nv_bfloat162*)(g_Blo + (size_t)(n0 + r) * KO + k0 + cc) = lp;
    }
}

// ==================================================================
// Kernel A: fused projections (k-split, full occupancy)
// ==================================================================
#define GROUP    4
#define PTHREADS 544
#define KQ       4
#define CW       136
__global__ __launch_bounds__(PTHREADS) void proj_kernel(
    const float* __restrict__ x,
    const float* __restrict__ b_ar, const float* __restrict__ b_f,
    const float* __restrict__ b_r)
{
    __shared__ float xs[GROUP][IN_];
    __shared__ float red[GROUP][KQ][CW];
    const int b0 = blockIdx.x * GROUP;

    for (int i = threadIdx.x; i < GROUP * (IN_ / 4); i += PTHREADS) {
        int g = i >> 9, k4 = i & 511;
        ((float4*)xs[g])[k4] = ((const float4*)(x + (size_t)(b0 + g) * IN_))[k4];
    }
    __syncthreads();

    const int t = threadIdx.x, col = t % CW, kq = t / CW;
    float acc[GROUP] = {0.f, 0.f, 0.f, 0.f};
    if (col < NPAD) {
        const int kbase = kq * (IN_ / KQ);
        const float* wp = g_W + (size_t)kbase * NPAD + col;
        #pragma unroll 8
        for (int k = 0; k < IN_ / KQ; k++) {
            float w = wp[(size_t)k * NPAD];
            int kk = kbase + k;
            acc[0] = fmaf(xs[0][kk], w, acc[0]);
            acc[1] = fmaf(xs[1][kk], w, acc[1]);
            acc[2] = fmaf(xs[2][kk], w, acc[2]);
            acc[3] = fmaf(xs[3][kk], w, acc[3]);
        }
    }
    #pragma unroll
    for (int g = 0; g < GROUP; g++) red[g][kq][col] = acc[g];
    __syncthreads();

    if (kq == 0 && col < 130) {
        float bias = (col < 64) ? b_ar[col] : (col == 64 ? b_f[0] : b_r[col - 65]);
        #pragma unroll
        for (int g = 0; g < GROUP; g++) {
            float s = red[g][0][col] + red[g][1][col] + red[g][2][col] + red[g][3][col] + bias;
            int b = b0 + g;
            if (col < 64)       g_q[(size_t)b * MEM_ + col] = s;
            else if (col == 64) g_xf[b] = s;
            else                g_xr[(size_t)b * RCOLS + (col - 65)] = s;
        }
    }
}

// ==================================================================
// Kernel B: memory-fused (recalls + gated update); act/pas -> bf16 hi/lo
// ==================================================================
__device__ __forceinline__ float blockReduce256(float v, float* red8, int isSum)
{
    #pragma unroll
    for (int o = 16; o; o >>= 1) {
        float u = __shfl_xor_sync(0xffffffffu, v, o);
        v = isSum ? (v + u) : fmaxf(v, u);
    }
    if ((threadIdx.x & 31) == 0) red8[threadIdx.x >> 5] = v;
    __syncthreads();
    float r = red8[0];
    #pragma unroll
    for (int i = 1; i < 8; i++) r = isSum ? (r + red8[i]) : fmaxf(r, red8[i]);
    __syncthreads();
    return r;
}

__global__ __launch_bounds__(256) void mem_kernel(
    const float* __restrict__ memory,
    const float* __restrict__ W_pr, const float* __restrict__ b_pr,
    const float* __restrict__ W_f,
    const float* __restrict__ W_r,
    float* __restrict__ new_memory)
{
    extern __shared__ float sm[];
    float* ms   = sm;               // 128*65
    float* ws   = ms  + 8320;       // 64*66
    float* rem  = ws  + 4224;       // 128*66
    float* qs   = rem + 8448;       // 64
    float* wpr  = qs  + 64;         // 64
    float* xrs  = wpr + 64;         // 66
    float* s1   = xrs + 66;         // 128
    float* s2   = s1  + 128;        // 128
    float* red8 = s2  + 128;        // 8

    const int b = blockIdx.x;
    const int t = threadIdx.x;
    const float* memb = memory + (size_t)b * NS * MEM_;

    for (int i = t; i < NS * MEM_; i += 256) {
        int n = i >> 6, m = i & 63;
        ms[n * 65 + m] = memb[i];
    }
    for (int i = t; i < 64 * 66; i += 256) {
        int k = i / 66, j = i - k * 66;
        ws[i] = (j < 65) ? W_r[(size_t)(IN_ + k) * RCOLS + j] : W_f[IN_ + k];
    }
    if (t < 64)  { qs[t] = g_q[(size_t)b * MEM_ + t]; wpr[t] = W_pr[t]; }
    if (t < 65)  { xrs[t] = g_xr[(size_t)b * RCOLS + t]; }
    __syncthreads();

    float s1v = -1e30f, s2v = -1e30f;
    if (t < NS) {
        float a = 0.f, p = 0.f;
        #pragma unroll 8
        for (int k = 0; k < MEM_; k++) {
            float mv = ms[t * 65 + k];
            a = fmaf(mv, qs[k], a);
            p = fmaf(mv, wpr[k], p);
        }
        s1v = a;
        s2v = p + b_pr[0];
    }
    float max1 = blockReduce256(s1v, red8, 0);
    float max2 = blockReduce256(s2v, red8, 0);
    float e1 = (t < NS) ? expf(s1v - max1) : 0.f;
    float e2 = (t < NS) ? expf(s2v - max2) : 0.f;
    float sum1 = blockReduce256(e1, red8, 1);
    float sum2 = blockReduce256(e2, red8, 1);
    if (t < NS) { s1[t] = e1 / sum1; s2[t] = e2 / sum2; }
    __syncthreads();

    if (t < MEM_) {
        float act = 0.f, pas = 0.f;
        #pragma unroll 4
        for (int n = 0; n < NS; n++) {
            float mv = ms[n * 65 + t];
            act = fmaf(s1[n], mv, act);
            pas = fmaf(s2[n], mv, pas);
        }
        __nv_bfloat16 h, l;
        split_bf16(act, h, l);
        g_Ahi[(size_t)b * KO + IN_ + t] = h;
        g_Alo[(size_t)b * KO + IN_ + t] = l;
        split_bf16(pas, h, l);
        g_Ahi[(size_t)b * KO + IN_ + MEM_ + t] = h;
        g_Alo[(size_t)b * KO + IN_ + MEM_ + t] = l;
    }

    if (t < 132) {
        const int j   = t % 66;
        const int nlo = (t / 66) * 64;
        float w[64];
        #pragma unroll
        for (int k = 0; k < 64; k++) w[k] = ws[k * 66 + j];
        const float base = (j < 65) ? xrs[j] : g_xf[b];
        #pragma unroll 2
        for (int n = nlo; n < nlo + 64; n++) {
            float acc = base;
            #pragma unroll
            for (int k = 0; k < 64; k++)
                acc = fmaf(ms[n * 65 + k], w[k], acc);
            if (j < 65) rem[n * 66 + j] = acc;
            else        rem[n * 66 + 65] = 1.1f / (1.f + expf(-acc));
        }
    }
    __syncthreads();

    float* nm = new_memory + (size_t)b * NS * MEM_;
    for (int i = t; i < NS * MEM_; i += 256) {
        int n = i >> 6, m = i & 63;
        float f    = rem[n * 66 + 65];
        float gate = rem[n * 66 + 64];
        nm[i] = fmaf(ms[n * 65 + m], f, gate * rem[n * 66 + m]);
    }
}

// ==================================================================
// Kernel C: mma.sync bf16 split GEMM.
// C[64,128] per CTA, 128 threads (4 warps, warp tile 32x64).
// K loop: 3 products x 68 chunks of k=32, cp.async double buffer.
// ==================================================================
#define CTA_M   64
#define CTA_N   128
#define KCHUNK  32
#define NKC     68                       // 2176/32
#define NIT     (3 * NKC)                // 204
#define A_ST    4096                     // 2 subs * 64 rows * 32B
#define B_ST    8192                     // 2 subs * 128 rows * 32B
#define STAGE_B (A_ST + B_ST)            // 12288

__global__ __launch_bounds__(128) void out_gemm_mma(
    const float* __restrict__ b_o, float* __restrict__ out)
{
    __shared__ __align__(128) char sm[2 * STAGE_B];

    const int tid  = threadIdx.x;
    const int wid  = tid >> 5;
    const int lane = tid & 31;
    const int wm   = wid >> 1;           // 0..1
    const int wn   = wid & 1;            // 0..1
    const int br   = blockIdx.y * CTA_M;
    const int bc   = blockIdx.x * CTA_N;
    const uint32_t smem = smem_u32(sm);

    float c[2][8][4];
    #pragma unroll
    for (int i = 0; i < 2; i++)
        #pragma unroll
        for (int j = 0; j < 8; j++)
            #pragma unroll
            for (int q = 0; q < 4; q++) c[i][j][q] = 0.f;

    // per-lane ldmatrix source offsets (within a sub-tile), constant over loop
    const int lrow = ((lane >> 3) & 1) * 8 + (lane & 7);
    const int lh   = (lane >> 4) & 1;

    // ---- prefetch helper (inlined via lambda-like macro) ----
    auto prefetch = [&](int it) {
        const int p  = it / NKC;
        const int kc = it - p * NKC;
        const int k0 = kc * KCHUNK;
        const int st = it & 1;
        const __nv_bfloat16* Asrc = (p == 2) ? g_Alo : g_Ahi;
        const __nv_bfloat16* Bsrc = (p == 1) ? g_Blo : g_Bhi;
        const uint32_t sA = smem + st * STAGE_B;
        const uint32_t sB = sA + A_ST;
        #pragma unroll
        for (int q = 0; q < 2; q++) {
            int u = tid + q * 128;
            int r = u >> 2, s = (u >> 1) & 1, h = u & 1;
            const void* src = Asrc + (size_t)(br + r) * KO + k0 + s * 16 + h * 8;
            uint32_t dst = sA + s * 2048 + r * 32 + ((h ^ ((r >> 2) & 1)) << 4);
            cp16(dst, src);
        }
        #pragma unroll
        for (int q = 0; q < 4; q++) {
            int u = tid + q * 128;
            int n = u >> 2, s = (u >> 1) & 1, h = u & 1;
            const void* src = Bsrc + (size_t)(bc + n) * KO + k0 + s * 16 + h * 8;
            uint32_t dst = sB + s * 4096 + n * 32 + ((h ^ ((n >> 2) & 1)) << 4);
            cp16(dst, src);
        }
        CP_COMMIT();
    };

    prefetch(0);

    for (int it = 0; it < NIT; it++) {
        if (it + 1 < NIT) { prefetch(it + 1); CP_WAIT(1); }
        else              { CP_WAIT(0); }
        __syncthreads();

        const uint32_t sA = smem + (it & 1) * STAGE_B;
        const uint32_t sB = sA + A_ST;

        #pragma unroll
        for (int s = 0; s < 2; s++) {             // two k16 subs
            uint32_t a[2][4];
            #pragma unroll
            for (int f = 0; f < 2; f++) {
                int rr = wm * 32 + f * 16 + lrow;
                uint32_t addr = sA + s * 2048 + rr * 32 + ((lh ^ ((rr >> 2) & 1)) << 4);
                ldm_x4(a[f], addr);
            }
            uint32_t b[8][2];
            #pragma unroll
            for (int j = 0; j < 4; j++) {
                int nn = wn * 64 + j * 16 + lrow;
                uint32_t addr = sB + s * 4096 + nn * 32 + ((lh ^ ((nn >> 2) & 1)) << 4);
                uint32_t r4[4];
                ldm_x4(r4, addr);
                b[2 * j][0]     = r4[0];
                b[2 * j + 1][0] = r4[1];
                b[2 * j][1]     = r4[2];
                b[2 * j + 1][1] = r4[3];
            }
            #pragma unroll
            for (int mf = 0; mf < 2; mf++)
                #pragma unroll
                for (int nf = 0; nf < 8; nf++)
                    mma16816(c[mf][nf], a[mf], b[nf]);
        }
        __syncthreads();
    }

    // ---- epilogue: direct stores with bias ----
    const int g  = lane >> 2;
    const int tg = lane & 3;
    #pragma unroll
    for (int nf = 0; nf < 8; nf++) {
        const int col = bc + wn * 64 + nf * 8 + tg * 2;
        const float2 bb = *(const float2*)(b_o + col);
        #pragma unroll
        for (int mf = 0; mf < 2; mf++) {
            const int row0 = br + wm * 32 + mf * 16 + g;
            float2 v0 = make_float2(c[mf][nf][0] + bb.x, c[mf][nf][1] + bb.y);
            float2 v1 = make_float2(c[mf][nf][2] + bb.x, c[mf][nf][3] + bb.y);
            *(float2*)(out + (size_t)row0 * OUT_ + col)       = v0;
            *(float2*)(out + (size_t)(row0 + 8) * OUT_ + col) = v1;
        }
    }
}

// ==================================================================
// Launch
// ==================================================================
extern "C" void kernel_launch(void* const* d_in, const int* in_sizes, int n_in,
                              void* d_out, int out_size)
{
    const float* x    = (const float*)d_in[0];
    const float* mem  = (const float*)d_in[1];
    const float* W_ar = (const float*)d_in[2];
    const float* b_ar = (const float*)d_in[3];
    const float* W_pr = (const float*)d_in[4];
    const float* b_pr = (const float*)d_in[5];
    const float* W_f  = (const float*)d_in[6];
    const float* b_f  = (const float*)d_in[7];
    const float* W_r  = (const float*)d_in[8];
    const float* b_r  = (const float*)d_in[9];
    const float* W_o  = (const float*)d_in[10];
    const float* b_o  = (const float*)d_in[11];

    float* out     = (float*)d_out;
    float* new_mem = out + (size_t)B_ * OUT_;

    const int smemB = (8320 + 4224 + 8448 + 64 + 64 + 66 + 128 + 128 + 8) * 4;
    cudaFuncSetAttribute(mem_kernel, cudaFuncAttributeMaxDynamicSharedMemorySize, smemB);

    pack_kernel<<<(IN_ * NPAD + 255) / 256, 256>>>(W_ar, W_f, W_r);
    conv_x_kernel<<<(B_ * IN_ / 8) / 256, 256>>>(x);
    {
        dim3 g(KO / 32, OUT_ / 32);
        conv_B_kernel<<<g, 256>>>(W_o);
    }
    proj_kernel<<<B_ / GROUP, PTHREADS>>>(x, b_ar, b_f, b_r);
    mem_kernel<<<B_, 256, smemB>>>(mem, W_pr, b_pr, W_f, W_r, new_mem);
    {
        dim3 g(OUT_ / CTA_N, B_ / CTA_M);   // (16, 8)
        out_gemm_mma<<<g, 128>>>(b_o, out);
    }
}

// round 5
// speedup vs baseline: 2.1868x; 1.1547x over previous
#include <cuda_runtime.h>
#include <cuda_bf16.h>
#include <math.h>
#include <cstdint>

// Problem constants
#define B_    512
#define NS    128
#define IN_   2048
#define MEM_  64
#define OUT_  2048
#define RCOLS 65
#define KO    2176          // IN_ + 2*MEM_
#define NPAD  132

// ------------------------------------------------------------------
// Scratch (device globals)
// ------------------------------------------------------------------
__device__ float g_q  [B_ * MEM_];
__device__ float g_xf [B_];
__device__ float g_xr [B_ * RCOLS];
__device__ float g_W  [IN_ * NPAD];
__device__ __nv_bfloat16 g_Ahi[B_ * KO];       // [512][2176]  (x | act | pas)
__device__ __nv_bfloat16 g_Alo[B_ * KO];
__device__ __nv_bfloat16 g_Bhi[OUT_ * KO];     // [2048][2176] = W_o^T
__device__ __nv_bfloat16 g_Blo[OUT_ * KO];

// ------------------------------------------------------------------
// Helpers
// ------------------------------------------------------------------
__device__ __forceinline__ uint32_t smem_u32(const void* p) {
    uint32_t a;
    asm("{ .reg .u64 t; cvta.to.shared.u64 t, %1; cvt.u32.u64 %0, t; }"
        : "=r"(a) : "l"(p));
    return a;
}
__device__ __forceinline__ void cp16(uint32_t dst, const void* src) {
    asm volatile("cp.async.cg.shared.global [%0], [%1], 16;" :: "r"(dst), "l"(src));
}
#define CP_COMMIT()  asm volatile("cp.async.commit_group;" ::: "memory")
#define CP_WAIT(n)   asm volatile("cp.async.wait_group %0;" :: "n"(n) : "memory")

__device__ __forceinline__ void ldm_x4(uint32_t* r, uint32_t addr) {
    asm volatile("ldmatrix.sync.aligned.m8n8.x4.shared.b16 {%0,%1,%2,%3}, [%4];"
        : "=r"(r[0]), "=r"(r[1]), "=r"(r[2]), "=r"(r[3]) : "r"(addr));
}
__device__ __forceinline__ void mma16816(float* c, const uint32_t* a, const uint32_t* b) {
    asm volatile(
        "mma.sync.aligned.m16n8k16.row.col.f32.bf16.bf16.f32 "
        "{%0,%1,%2,%3}, {%4,%5,%6,%7}, {%8,%9}, {%0,%1,%2,%3};"
        : "+f"(c[0]), "+f"(c[1]), "+f"(c[2]), "+f"(c[3])
        : "r"(a[0]), "r"(a[1]), "r"(a[2]), "r"(a[3]), "r"(b[0]), "r"(b[1]));
}
__device__ __forceinline__ void split_bf16(float v, __nv_bfloat16& h, __nv_bfloat16& l) {
    h = __float2bfloat16(v);
    l = __float2bfloat16(v - __bfloat162float(h));
}

// ==================================================================
// Prep kernels
// ==================================================================
__global__ __launch_bounds__(256) void pack_kernel(
    const float* __restrict__ W_ar, const float* __restrict__ W_f,
    const float* __restrict__ W_r)
{
    int idx = blockIdx.x * 256 + threadIdx.x;
    if (idx >= IN_ * NPAD) return;
    int k = idx / NPAD, c = idx - k * NPAD;
    float v = 0.f;
    if (c < 64)       v = W_ar[(size_t)k * 64 + c];
    else if (c == 64) v = W_f[k];
    else if (c < 130) v = W_r[(size_t)k * RCOLS + (c - 65)];
    g_W[idx] = v;
}

// x -> bf16 hi/lo into g_A*(cols 0..2047)
__global__ __launch_bounds__(256) void conv_x_kernel(const float* __restrict__ x)
{
    int i8 = blockIdx.x * 256 + threadIdx.x;       // 512*2048/8 = 131072
    int row = i8 >> 8;
    int col = (i8 & 255) * 8;
    const float4 v0 = *(const float4*)(x + (size_t)row * IN_ + col);
    const float4 v1 = *(const float4*)(x + (size_t)row * IN_ + col + 4);
    __nv_bfloat16 h[8], l[8];
    const float vv[8] = {v0.x, v0.y, v0.z, v0.w, v1.x, v1.y, v1.z, v1.w};
    #pragma unroll
    for (int j = 0; j < 8; j++) split_bf16(vv[j], h[j], l[j]);
    *(uint4*)(g_Ahi + (size_t)row * KO + col) = *(const uint4*)h;
    *(uint4*)(g_Alo + (size_t)row * KO + col) = *(const uint4*)l;
}

// W_o [K=2176][N=2048] -> g_B* [N][K] bf16 hi/lo (tiled transpose)
__global__ __launch_bounds__(256) void conv_B_kernel(const float* __restrict__ W_o)
{
    __shared__ float t[32][33];
    const int k0 = blockIdx.x * 32;
    const int n0 = blockIdx.y * 32;
    const int tid = threadIdx.x;
    #pragma unroll
    for (int p = 0; p < 4; p++) {
        int r = (tid >> 5) + p * 8, c = tid & 31;
        t[r][c] = W_o[(size_t)(k0 + r) * OUT_ + n0 + c];
    }
    __syncthreads();
    #pragma unroll
    for (int p = 0; p < 2; p++) {
        int r = (tid >> 4) + p * 16;           // n within tile
        int cc = (tid & 15) * 2;               // k pair
        float v0 = t[cc][r], v1 = t[cc + 1][r];
        __nv_bfloat16 h0, l0, h1, l1;
        split_bf16(v0, h0, l0);
        split_bf16(v1, h1, l1);
        __nv_bfloat162 hp; hp.x = h0; hp.y = h1;
        __nv_bfloat162 lp; lp.x = l0; lp.y = l1;
        *(__nv_bfloat162*)(g_Bhi + (size_t)(n0 + r) * KO + k0 + cc) = hp;
        *(__nv_bfloat162*)(g_Blo + (size_t)(n0 + r) * KO + k0 + cc) = lp;
    }
}

// ==================================================================
// Kernel A: fused projections. float4 W loads: 16 FMA per LDG.128.
// grid = 128 (GROUP=4 rows), 528 threads = 33 col4-groups x 16 k-slices.
// ==================================================================
#define GROUP 4
#define CW4   33                  // 132/4 float4 columns
#define KQ2   16                  // k-slices (128 k each)
#define PTH   (CW4 * KQ2)         // 528
#define KSL   (IN_ / KQ2)         // 128

__global__ __launch_bounds__(PTH) void proj_kernel(
    const float* __restrict__ x,
    const float* __restrict__ b_ar, const float* __restrict__ b_f,
    const float* __restrict__ b_r)
{
    extern __shared__ float psm[];
    float* xs  = psm;                      // [GROUP][IN_]   32 KB
    float* red = psm + GROUP * IN_;        // [GROUP][KQ2][132]  33.8 KB
    const int b0 = blockIdx.x * GROUP;

    for (int i = threadIdx.x; i < GROUP * (IN_ / 4); i += PTH) {
        int g = i >> 9, k4 = i & 511;
        ((float4*)(xs + g * IN_))[k4] =
            ((const float4*)(x + (size_t)(b0 + g) * IN_))[k4];
    }
    __syncthreads();

    const int t  = threadIdx.x;
    const int c4 = t % CW4;
    const int kq = t / CW4;
    const int kbase = kq * KSL;

    float4 acc[GROUP];
    #pragma unroll
    for (int g = 0; g < GROUP; g++) acc[g] = make_float4(0.f, 0.f, 0.f, 0.f);

    const float4* wp = (const float4*)(g_W + (size_t)kbase * NPAD) + c4;
    #pragma unroll 8
    for (int k = 0; k < KSL; k++) {
        const float4 w = wp[(size_t)k * (NPAD / 4)];
        const int kk = kbase + k;
        #pragma unroll
        for (int g = 0; g < GROUP; g++) {
            const float xv = xs[g * IN_ + kk];
            acc[g].x = fmaf(xv, w.x, acc[g].x);
            acc[g].y = fmaf(xv, w.y, acc[g].y);
            acc[g].z = fmaf(xv, w.z, acc[g].z);
            acc[g].w = fmaf(xv, w.w, acc[g].w);
        }
    }
    #pragma unroll
    for (int g = 0; g < GROUP; g++)
        *(float4*)&red[(g * KQ2 + kq) * NPAD + c4 * 4] = acc[g];
    __syncthreads();

    if (t < 130) {
        float bias = (t < 64) ? b_ar[t] : (t == 64 ? b_f[0] : b_r[t - 65]);
        #pragma unroll
        for (int g = 0; g < GROUP; g++) {
            float s = bias;
            #pragma unroll
            for (int q = 0; q < KQ2; q++)
                s += red[(g * KQ2 + q) * NPAD + t];
            const int b = b0 + g;
            if (t < 64)       g_q[(size_t)b * MEM_ + t] = s;
            else if (t == 64) g_xf[b] = s;
            else              g_xr[(size_t)b * RCOLS + (t - 65)] = s;
        }
    }
}
#define PROJ_SMEM ((GROUP * IN_ + GROUP * KQ2 * NPAD) * 4)   // 66560 B

// ==================================================================
// Kernel B: memory-fused (recalls + gated update); act/pas -> bf16 hi/lo
// ==================================================================
__device__ __forceinline__ float blockReduce256(float v, float* red8, int isSum)
{
    #pragma unroll
    for (int o = 16; o; o >>= 1) {
        float u = __shfl_xor_sync(0xffffffffu, v, o);
        v = isSum ? (v + u) : fmaxf(v, u);
    }
    if ((threadIdx.x & 31) == 0) red8[threadIdx.x >> 5] = v;
    __syncthreads();
    float r = red8[0];
    #pragma unroll
    for (int i = 1; i < 8; i++) r = isSum ? (r + red8[i]) : fmaxf(r, red8[i]);
    __syncthreads();
    return r;
}

__global__ __launch_bounds__(256) void mem_kernel(
    const float* __restrict__ memory,
    const float* __restrict__ W_pr, const float* __restrict__ b_pr,
    const float* __restrict__ W_f,
    const float* __restrict__ W_r,
    float* __restrict__ new_memory)
{
    extern __shared__ float sm[];
    float* ms   = sm;               // 128*65
    float* ws   = ms  + 8320;       // 64*66
    float* rem  = ws  + 4224;       // 128*66
    float* qs   = rem + 8448;       // 64
    float* wpr  = qs  + 64;         // 64
    float* xrs  = wpr + 64;         // 66
    float* s1   = xrs + 66;         // 128
    float* s2   = s1  + 128;        // 128
    float* red8 = s2  + 128;        // 8

    const int b = blockIdx.x;
    const int t = threadIdx.x;
    const float* memb = memory + (size_t)b * NS * MEM_;

    for (int i = t; i < NS * MEM_; i += 256) {
        int n = i >> 6, m = i & 63;
        ms[n * 65 + m] = memb[i];
    }
    for (int i = t; i < 64 * 66; i += 256) {
        int k = i / 66, j = i - k * 66;
        ws[i] = (j < 65) ? W_r[(size_t)(IN_ + k) * RCOLS + j] : W_f[IN_ + k];
    }
    if (t < 64)  { qs[t] = g_q[(size_t)b * MEM_ + t]; wpr[t] = W_pr[t]; }
    if (t < 65)  { xrs[t] = g_xr[(size_t)b * RCOLS + t]; }
    __syncthreads();

    float s1v = -1e30f, s2v = -1e30f;
    if (t < NS) {
        float a = 0.f, p = 0.f;
        #pragma unroll 8
        for (int k = 0; k < MEM_; k++) {
            float mv = ms[t * 65 + k];
            a = fmaf(mv, qs[k], a);
            p = fmaf(mv, wpr[k], p);
        }
        s1v = a;
        s2v = p + b_pr[0];
    }
    float max1 = blockReduce256(s1v, red8, 0);
    float max2 = blockReduce256(s2v, red8, 0);
    float e1 = (t < NS) ? expf(s1v - max1) : 0.f;
    float e2 = (t < NS) ? expf(s2v - max2) : 0.f;
    float sum1 = blockReduce256(e1, red8, 1);
    float sum2 = blockReduce256(e2, red8, 1);
    if (t < NS) { s1[t] = e1 / sum1; s2[t] = e2 / sum2; }
    __syncthreads();

    if (t < MEM_) {
        float act = 0.f, pas = 0.f;
        #pragma unroll 4
        for (int n = 0; n < NS; n++) {
            float mv = ms[n * 65 + t];
            act = fmaf(s1[n], mv, act);
            pas = fmaf(s2[n], mv, pas);
        }
        __nv_bfloat16 h, l;
        split_bf16(act, h, l);
        g_Ahi[(size_t)b * KO + IN_ + t] = h;
        g_Alo[(size_t)b * KO + IN_ + t] = l;
        split_bf16(pas, h, l);
        g_Ahi[(size_t)b * KO + IN_ + MEM_ + t] = h;
        g_Alo[(size_t)b * KO + IN_ + MEM_ + t] = l;
    }

    if (t < 132) {
        const int j   = t % 66;
        const int nlo = (t / 66) * 64;
        float w[64];
        #pragma unroll
        for (int k = 0; k < 64; k++) w[k] = ws[k * 66 + j];
        const float base = (j < 65) ? xrs[j] : g_xf[b];
        #pragma unroll 2
        for (int n = nlo; n < nlo + 64; n++) {
            float acc = base;
            #pragma unroll
            for (int k = 0; k < 64; k++)
                acc = fmaf(ms[n * 65 + k], w[k], acc);
            if (j < 65) rem[n * 66 + j] = acc;
            else        rem[n * 66 + 65] = 1.1f / (1.f + expf(-acc));
        }
    }
    __syncthreads();

    float* nm = new_memory + (size_t)b * NS * MEM_;
    for (int i = t; i < NS * MEM_; i += 256) {
        int n = i >> 6, m = i & 63;
        float f    = rem[n * 66 + 65];
        float gate = rem[n * 66 + 64];
        nm[i] = fmaf(ms[n * 65 + m], f, gate * rem[n * 66 + m]);
    }
}

// ==================================================================
// Kernel C: mma.sync bf16 split GEMM.
// C[64,128] per CTA, 128 threads (4 warps, warp tile 32x64).
// K loop: 3 products x 68 chunks of k=32, cp.async double buffer.
// ==================================================================
#define CTA_M   64
#define CTA_N   128
#define KCHUNK  32
#define NKC     68                       // 2176/32
#define NIT     (3 * NKC)                // 204
#define A_ST    4096                     // 2 subs * 64 rows * 32B
#define B_ST    8192                     // 2 subs * 128 rows * 32B
#define STAGE_B (A_ST + B_ST)            // 12288

__global__ __launch_bounds__(128) void out_gemm_mma(
    const float* __restrict__ b_o, float* __restrict__ out)
{
    __shared__ __align__(128) char sm[2 * STAGE_B];

    const int tid  = threadIdx.x;
    const int wid  = tid >> 5;
    const int lane = tid & 31;
    const int wm   = wid >> 1;           // 0..1
    const int wn   = wid & 1;            // 0..1
    const int br   = blockIdx.y * CTA_M;
    const int bc   = blockIdx.x * CTA_N;
    const uint32_t smem = smem_u32(sm);

    float c[2][8][4];
    #pragma unroll
    for (int i = 0; i < 2; i++)
        #pragma unroll
        for (int j = 0; j < 8; j++)
            #pragma unroll
            for (int q = 0; q < 4; q++) c[i][j][q] = 0.f;

    const int lrow = ((lane >> 3) & 1) * 8 + (lane & 7);
    const int lh   = (lane >> 4) & 1;

    auto prefetch = [&](int it) {
        const int p  = it / NKC;
        const int kc = it - p * NKC;
        const int k0 = kc * KCHUNK;
        const int st = it & 1;
        const __nv_bfloat16* Asrc = (p == 2) ? g_Alo : g_Ahi;
        const __nv_bfloat16* Bsrc = (p == 1) ? g_Blo : g_Bhi;
        const uint32_t sA = smem + st * STAGE_B;
        const uint32_t sB = sA + A_ST;
        #pragma unroll
        for (int q = 0; q < 2; q++) {
            int u = tid + q * 128;
            int r = u >> 2, s = (u >> 1) & 1, h = u & 1;
            const void* src = Asrc + (size_t)(br + r) * KO + k0 + s * 16 + h * 8;
            uint32_t dst = sA + s * 2048 + r * 32 + ((h ^ ((r >> 2) & 1)) << 4);
            cp16(dst, src);
        }
        #pragma unroll
        for (int q = 0; q < 4; q++) {
            int u = tid + q * 128;
            int n = u >> 2, s = (u >> 1) & 1, h = u & 1;
            const void* src = Bsrc + (size_t)(bc + n) * KO + k0 + s * 16 + h * 8;
            uint32_t dst = sB + s * 4096 + n * 32 + ((h ^ ((n >> 2) & 1)) << 4);
            cp16(dst, src);
        }
        CP_COMMIT();
    };

    prefetch(0);

    for (int it = 0; it < NIT; it++) {
        if (it + 1 < NIT) { prefetch(it + 1); CP_WAIT(1); }
        else              { CP_WAIT(0); }
        __syncthreads();

        const uint32_t sA = smem + (it & 1) * STAGE_B;
        const uint32_t sB = sA + A_ST;

        #pragma unroll
        for (int s = 0; s < 2; s++) {
            uint32_t a[2][4];
            #pragma unroll
            for (int f = 0; f < 2; f++) {
                int rr = wm * 32 + f * 16 + lrow;
                uint32_t addr = sA + s * 2048 + rr * 32 + ((lh ^ ((rr >> 2) & 1)) << 4);
                ldm_x4(a[f], addr);
            }
            uint32_t b[8][2];
            #pragma unroll
            for (int j = 0; j < 4; j++) {
                int nn = wn * 64 + j * 16 + lrow;
                uint32_t addr = sB + s * 4096 + nn * 32 + ((lh ^ ((nn >> 2) & 1)) << 4);
                uint32_t r4[4];
                ldm_x4(r4, addr);
                b[2 * j][0]     = r4[0];
                b[2 * j + 1][0] = r4[1];
                b[2 * j][1]     = r4[2];
                b[2 * j + 1][1] = r4[3];
            }
            #pragma unroll
            for (int mf = 0; mf < 2; mf++)
                #pragma unroll
                for (int nf = 0; nf < 8; nf++)
                    mma16816(c[mf][nf], a[mf], b[nf]);
        }
        __syncthreads();
    }

    const int g  = lane >> 2;
    const int tg = lane & 3;
    #pragma unroll
    for (int nf = 0; nf < 8; nf++) {
        const int col = bc + wn * 64 + nf * 8 + tg * 2;
        const float2 bb = *(const float2*)(b_o + col);
        #pragma unroll
        for (int mf = 0; mf < 2; mf++) {
            const int row0 = br + wm * 32 + mf * 16 + g;
            float2 v0 = make_float2(c[mf][nf][0] + bb.x, c[mf][nf][1] + bb.y);
            float2 v1 = make_float2(c[mf][nf][2] + bb.x, c[mf][nf][3] + bb.y);
            *(float2*)(out + (size_t)row0 * OUT_ + col)       = v0;
            *(float2*)(out + (size_t)(row0 + 8) * OUT_ + col) = v1;
        }
    }
}

// ==================================================================
// Launch
// ==================================================================
extern "C" void kernel_launch(void* const* d_in, const int* in_sizes, int n_in,
                              void* d_out, int out_size)
{
    const float* x    = (const float*)d_in[0];
    const float* mem  = (const float*)d_in[1];
    const float* W_ar = (const float*)d_in[2];
    const float* b_ar = (const float*)d_in[3];
    const float* W_pr = (const float*)d_in[4];
    const float* b_pr = (const float*)d_in[5];
    const float* W_f  = (const float*)d_in[6];
    const float* b_f  = (const float*)d_in[7];
    const float* W_r  = (const float*)d_in[8];
    const float* b_r  = (const float*)d_in[9];
    const float* W_o  = (const float*)d_in[10];
    const float* b_o  = (const float*)d_in[11];

    float* out     = (float*)d_out;
    float* new_mem = out + (size_t)B_ * OUT_;

    const int smemB = (8320 + 4224 + 8448 + 64 + 64 + 66 + 128 + 128 + 8) * 4;
    cudaFuncSetAttribute(mem_kernel, cudaFuncAttributeMaxDynamicSharedMemorySize, smemB);
    cudaFuncSetAttribute(proj_kernel, cudaFuncAttributeMaxDynamicSharedMemorySize, PROJ_SMEM);

    pack_kernel<<<(IN_ * NPAD + 255) / 256, 256>>>(W_ar, W_f, W_r);
    conv_x_kernel<<<(B_ * IN_ / 8) / 256, 256>>>(x);
    {
        dim3 g(KO / 32, OUT_ / 32);
        conv_B_kernel<<<g, 256>>>(W_o);
    }
    proj_kernel<<<B_ / GROUP, PTH, PROJ_SMEM>>>(x, b_ar, b_f, b_r);
    mem_kernel<<<B_, 256, smemB>>>(mem, W_pr, b_pr, W_f, W_r, new_mem);
    {
        dim3 g(OUT_ / CTA_N, B_ / CTA_M);   // (16, 8)
        out_gemm_mma<<<g, 128>>>(b_o, out);
    }
}

// round 6
// speedup vs baseline: 3.0781x; 1.4076x over previous
#include <cuda_runtime.h>
#include <cuda_bf16.h>
#include <math.h>
#include <cstdint>

// Problem constants
#define B_    512
#define NS    128
#define IN_   2048
#define MEM_  64
#define OUT_  2048
#define RCOLS 65
#define KO    2176          // IN_ + 2*MEM_
#define NPAD  132

// ------------------------------------------------------------------
// Scratch (device globals)
// ------------------------------------------------------------------
__device__ float g_q  [B_ * MEM_];
__device__ float g_xf [B_];
__device__ float g_xr [B_ * RCOLS];
__device__ float g_W  [IN_ * NPAD];
__device__ __nv_bfloat16 g_Ahi[B_ * KO];       // [512][2176]  (x | act | pas)
__device__ __nv_bfloat16 g_Alo[B_ * KO];
__device__ __nv_bfloat16 g_Bhi[OUT_ * KO];     // [2048][2176] = W_o^T
__device__ __nv_bfloat16 g_Blo[OUT_ * KO];

// ------------------------------------------------------------------
// Helpers
// ------------------------------------------------------------------
__device__ __forceinline__ uint32_t smem_u32(const void* p) {
    uint32_t a;
    asm("{ .reg .u64 t; cvta.to.shared.u64 t, %1; cvt.u32.u64 %0, t; }"
        : "=r"(a) : "l"(p));
    return a;
}
__device__ __forceinline__ void cp16(uint32_t dst, const void* src) {
    asm volatile("cp.async.cg.shared.global [%0], [%1], 16;" :: "r"(dst), "l"(src));
}
#define CP_COMMIT()  asm volatile("cp.async.commit_group;" ::: "memory")
#define CP_WAIT(n)   asm volatile("cp.async.wait_group %0;" :: "n"(n) : "memory")

__device__ __forceinline__ void ldm_x4(uint32_t* r, uint32_t addr) {
    asm volatile("ldmatrix.sync.aligned.m8n8.x4.shared.b16 {%0,%1,%2,%3}, [%4];"
        : "=r"(r[0]), "=r"(r[1]), "=r"(r[2]), "=r"(r[3]) : "r"(addr));
}
__device__ __forceinline__ void mma16816(float* c, const uint32_t* a, const uint32_t* b) {
    asm volatile(
        "mma.sync.aligned.m16n8k16.row.col.f32.bf16.bf16.f32 "
        "{%0,%1,%2,%3}, {%4,%5,%6,%7}, {%8,%9}, {%0,%1,%2,%3};"
        : "+f"(c[0]), "+f"(c[1]), "+f"(c[2]), "+f"(c[3])
        : "r"(a[0]), "r"(a[1]), "r"(a[2]), "r"(a[3]), "r"(b[0]), "r"(b[1]));
}
__device__ __forceinline__ void split_bf16(float v, __nv_bfloat16& h, __nv_bfloat16& l) {
    h = __float2bfloat16(v);
    l = __float2bfloat16(v - __bfloat162float(h));
}

// ==================================================================
// Prep kernels
// ==================================================================
__global__ __launch_bounds__(256) void pack_kernel(
    const float* __restrict__ W_ar, const float* __restrict__ W_f,
    const float* __restrict__ W_r)
{
    int idx = blockIdx.x * 256 + threadIdx.x;
    if (idx >= IN_ * NPAD) return;
    int k = idx / NPAD, c = idx - k * NPAD;
    float v = 0.f;
    if (c < 64)       v = W_ar[(size_t)k * 64 + c];
    else if (c == 64) v = W_f[k];
    else if (c < 130) v = W_r[(size_t)k * RCOLS + (c - 65)];
    g_W[idx] = v;
}

// W_o [K=2176][N=2048] -> g_B* [N][K] bf16 hi/lo (tiled transpose)
__global__ __launch_bounds__(256) void conv_B_kernel(const float* __restrict__ W_o)
{
    __shared__ float t[32][33];
    const int k0 = blockIdx.x * 32;
    const int n0 = blockIdx.y * 32;
    const int tid = threadIdx.x;
    #pragma unroll
    for (int p = 0; p < 4; p++) {
        int r = (tid >> 5) + p * 8, c = tid & 31;
        t[r][c] = W_o[(size_t)(k0 + r) * OUT_ + n0 + c];
    }
    __syncthreads();
    #pragma unroll
    for (int p = 0; p < 2; p++) {
        int r = (tid >> 4) + p * 16;           // n within tile
        int cc = (tid & 15) * 2;               // k pair
        float v0 = t[cc][r], v1 = t[cc + 1][r];
        __nv_bfloat16 h0, l0, h1, l1;
        split_bf16(v0, h0, l0);
        split_bf16(v1, h1, l1);
        __nv_bfloat162 hp; hp.x = h0; hp.y = h1;
        __nv_bfloat162 lp; lp.x = l0; lp.y = l1;
        *(__nv_bfloat162*)(g_Bhi + (size_t)(n0 + r) * KO + k0 + cc) = hp;
        *(__nv_bfloat162*)(g_Blo + (size_t)(n0 + r) * KO + k0 + cc) = lp;
    }
}

// ==================================================================
// Kernel A: fused projections + x->bf16 hi/lo conversion.
// grid = 128 (GROUP=4 rows), 528 threads = 33 col4-groups x 16 k-slices.
// ==================================================================
#define GROUP 4
#define CW4   33
#define KQ2   16
#define PTH   (CW4 * KQ2)         // 528
#define KSL   (IN_ / KQ2)         // 128

__global__ __launch_bounds__(PTH) void proj_kernel(
    const float* __restrict__ x,
    const float* __restrict__ b_ar, const float* __restrict__ b_f,
    const float* __restrict__ b_r)
{
    extern __shared__ float psm[];
    float* xs  = psm;                      // [GROUP][IN_]
    float* red = psm + GROUP * IN_;        // [GROUP][KQ2][132]
    const int b0 = blockIdx.x * GROUP;

    for (int i = threadIdx.x; i < GROUP * (IN_ / 4); i += PTH) {
        int g = i >> 9, k4 = i & 511;
        ((float4*)(xs + g * IN_))[k4] =
            ((const float4*)(x + (size_t)(b0 + g) * IN_))[k4];
    }
    __syncthreads();

    // x -> bf16 hi/lo (folded conv_x): 1024 chunks of 8, 528 threads
    for (int i = threadIdx.x; i < GROUP * (IN_ / 8); i += PTH) {
        int g = i >> 8, c8 = (i & 255) << 3;
        __nv_bfloat16 h[8], l[8];
        #pragma unroll
        for (int j = 0; j < 8; j++) split_bf16(xs[g * IN_ + c8 + j], h[j], l[j]);
        *(uint4*)(g_Ahi + (size_t)(b0 + g) * KO + c8) = *(const uint4*)h;
        *(uint4*)(g_Alo + (size_t)(b0 + g) * KO + c8) = *(const uint4*)l;
    }

    const int t  = threadIdx.x;
    const int c4 = t % CW4;
    const int kq = t / CW4;
    const int kbase = kq * KSL;

    float4 acc[GROUP];
    #pragma unroll
    for (int g = 0; g < GROUP; g++) acc[g] = make_float4(0.f, 0.f, 0.f, 0.f);

    const float4* wp = (const float4*)(g_W + (size_t)kbase * NPAD) + c4;
    #pragma unroll 8
    for (int k = 0; k < KSL; k++) {
        const float4 w = wp[(size_t)k * (NPAD / 4)];
        const int kk = kbase + k;
        #pragma unroll
        for (int g = 0; g < GROUP; g++) {
            const float xv = xs[g * IN_ + kk];
            acc[g].x = fmaf(xv, w.x, acc[g].x);
            acc[g].y = fmaf(xv, w.y, acc[g].y);
            acc[g].z = fmaf(xv, w.z, acc[g].z);
            acc[g].w = fmaf(xv, w.w, acc[g].w);
        }
    }
    #pragma unroll
    for (int g = 0; g < GROUP; g++)
        *(float4*)&red[(g * KQ2 + kq) * NPAD + c4 * 4] = acc[g];
    __syncthreads();

    if (t < 130) {
        float bias = (t < 64) ? b_ar[t] : (t == 64 ? b_f[0] : b_r[t - 65]);
        #pragma unroll
        for (int g = 0; g < GROUP; g++) {
            float s = bias;
            #pragma unroll
            for (int q = 0; q < KQ2; q++)
                s += red[(g * KQ2 + q) * NPAD + t];
            const int b = b0 + g;
            if (t < 64)       g_q[(size_t)b * MEM_ + t] = s;
            else if (t == 64) g_xf[b] = s;
            else              g_xr[(size_t)b * RCOLS + (t - 65)] = s;
        }
    }
}
#define PROJ_SMEM ((GROUP * IN_ + GROUP * KQ2 * NPAD) * 4)

// ==================================================================
// Kernel B: memory-fused. 288 threads; phase-2 spread over 264.
// ==================================================================
#define MTH 288
__device__ __forceinline__ float blockReduceM(float v, float* red9, int isSum)
{
    #pragma unroll
    for (int o = 16; o; o >>= 1) {
        float u = __shfl_xor_sync(0xffffffffu, v, o);
        v = isSum ? (v + u) : fmaxf(v, u);
    }
    if ((threadIdx.x & 31) == 0) red9[threadIdx.x >> 5] = v;
    __syncthreads();
    float r = red9[0];
    #pragma unroll
    for (int i = 1; i < 9; i++) r = isSum ? (r + red9[i]) : fmaxf(r, red9[i]);
    __syncthreads();
    return r;
}

__global__ __launch_bounds__(MTH) void mem_kernel(
    const float* __restrict__ memory,
    const float* __restrict__ W_pr, const float* __restrict__ b_pr,
    const float* __restrict__ W_f,
    const float* __restrict__ W_r,
    float* __restrict__ new_memory)
{
    extern __shared__ float sm[];
    float* ms   = sm;               // 128*65
    float* ws   = ms  + 8320;       // 64*66
    float* rem  = ws  + 4224;       // 128*66
    float* qs   = rem + 8448;       // 64
    float* wpr  = qs  + 64;         // 64
    float* xrs  = wpr + 64;         // 66
    float* s1   = xrs + 66;         // 128
    float* s2   = s1  + 128;        // 128
    float* red9 = s2  + 128;        // 9

    const int b = blockIdx.x;
    const int t = threadIdx.x;
    const float* memb = memory + (size_t)b * NS * MEM_;

    for (int i = t; i < NS * MEM_; i += MTH) {
        int n = i >> 6, m = i & 63;
        ms[n * 65 + m] = memb[i];
    }
    for (int i = t; i < 64 * 66; i += MTH) {
        int k = i / 66, j = i - k * 66;
        ws[i] = (j < 65) ? W_r[(size_t)(IN_ + k) * RCOLS + j] : W_f[IN_ + k];
    }
    if (t < 64)  { qs[t] = g_q[(size_t)b * MEM_ + t]; wpr[t] = W_pr[t]; }
    if (t < 65)  { xrs[t] = g_xr[(size_t)b * RCOLS + t]; }
    __syncthreads();

    float s1v = -1e30f, s2v = -1e30f;
    if (t < NS) {
        float a = 0.f, p = 0.f;
        #pragma unroll 8
        for (int k = 0; k < MEM_; k++) {
            float mv = ms[t * 65 + k];
            a = fmaf(mv, qs[k], a);
            p = fmaf(mv, wpr[k], p);
        }
        s1v = a;
        s2v = p + b_pr[0];
    }
    float max1 = blockReduceM(s1v, red9, 0);
    float max2 = blockReduceM(s2v, red9, 0);
    float e1 = (t < NS) ? expf(s1v - max1) : 0.f;
    float e2 = (t < NS) ? expf(s2v - max2) : 0.f;
    float sum1 = blockReduceM(e1, red9, 1);
    float sum2 = blockReduceM(e2, red9, 1);
    if (t < NS) { s1[t] = e1 / sum1; s2[t] = e2 / sum2; }
    __syncthreads();

    if (t < MEM_) {
        float act = 0.f, pas = 0.f;
        #pragma unroll 4
        for (int n = 0; n < NS; n++) {
            float mv = ms[n * 65 + t];
            act = fmaf(s1[n], mv, act);
            pas = fmaf(s2[n], mv, pas);
        }
        __nv_bfloat16 h, l;
        split_bf16(act, h, l);
        g_Ahi[(size_t)b * KO + IN_ + t] = h;
        g_Alo[(size_t)b * KO + IN_ + t] = l;
        split_bf16(pas, h, l);
        g_Ahi[(size_t)b * KO + IN_ + MEM_ + t] = h;
        g_Alo[(size_t)b * KO + IN_ + MEM_ + t] = l;
    }

    // Phase 2: rem + forget; 264 threads = 66 cols x 4 n-groups of 32
    if (t < 264) {
        const int j   = t % 66;
        const int nlo = (t / 66) * 32;
        float w[64];
        #pragma unroll
        for (int k = 0; k < 64; k++) w[k] = ws[k * 66 + j];
        const float base = (j < 65) ? xrs[j] : g_xf[b];
        #pragma unroll 2
        for (int n = nlo; n < nlo + 32; n++) {
            float acc = base;
            #pragma unroll
            for (int k = 0; k < 64; k++)
                acc = fmaf(ms[n * 65 + k], w[k], acc);
            if (j < 65) rem[n * 66 + j] = acc;
            else        rem[n * 66 + 65] = 1.1f / (1.f + expf(-acc));
        }
    }
    __syncthreads();

    float* nm = new_memory + (size_t)b * NS * MEM_;
    for (int i = t; i < NS * MEM_; i += MTH) {
        int n = i >> 6, m = i & 63;
        float f    = rem[n * 66 + 65];
        float gate = rem[n * 66 + 64];
        nm[i] = fmaf(ms[n * 65 + m], f, gate * rem[n * 66 + m]);
    }
}

// ==================================================================
// Kernel C: mma.sync bf16-split GEMM, 3 products fused per k-chunk.
// CTA 64x128, 256 threads (8 warps, warp tile 32x32), 68 iterations.
// Stage: Ahi 4K | Alo 4K | Bhi 8K | Blo 8K = 24KB, double-buffered.
// ==================================================================
#define CTA_M   64
#define CTA_N   128
#define KCHUNK  32
#define NKC     68
#define A_TB    4096
#define B_TB    8192
#define STAGE_B (2 * A_TB + 2 * B_TB)     // 24576

__device__ __forceinline__ uint32_t swz64(int r, int h) {
    return (uint32_t)((h ^ (r & 3) ^ ((r >> 2) & 1)) << 4);
}

__global__ __launch_bounds__(256) void out_gemm_mma(
    const float* __restrict__ b_o, float* __restrict__ out)
{
    __shared__ __align__(128) char smbuf[2 * STAGE_B];   // 48 KB

    const int tid  = threadIdx.x;
    const int wid  = tid >> 5;
    const int lane = tid & 31;
    const int wm   = wid & 1;            // 2 m-groups
    const int wn   = wid >> 1;           // 4 n-groups
    const int br   = blockIdx.y * CTA_M;
    const int bc   = blockIdx.x * CTA_N;
    const uint32_t smem = smem_u32(smbuf);

    float c[2][4][4];
    #pragma unroll
    for (int i = 0; i < 2; i++)
        #pragma unroll
        for (int j = 0; j < 4; j++)
            #pragma unroll
            for (int q = 0; q < 4; q++) c[i][j][q] = 0.f;

    const int lrow = ((lane >> 3) & 1) * 8 + (lane & 7);
    const int lh   = (lane >> 4) & 1;

    auto prefetch = [&](int kc) {
        const int k0 = kc * KCHUNK;
        const uint32_t sb = smem + (kc & 1) * STAGE_B;
        #pragma unroll
        for (int q = 0; q < 2; q++) {          // A hi/lo: 512 cp16
            int u = tid + q * 256;
            int tile = u >> 8, rm = u & 255;
            int r = rm >> 2, h = rm & 3;
            const __nv_bfloat16* src =
                (tile ? g_Alo : g_Ahi) + (size_t)(br + r) * KO + k0 + h * 8;
            cp16(sb + tile * A_TB + r * 64 + swz64(r, h), src);
        }
        #pragma unroll
        for (int q = 0; q < 4; q++) {          // B hi/lo: 1024 cp16
            int u = tid + q * 256;
            int tile = u >> 9, rm = u & 511;
            int n = rm >> 2, h = rm & 3;
            const __nv_bfloat16* src =
                (tile ? g_Blo : g_Bhi) + (size_t)(bc + n) * KO + k0 + h * 8;
            cp16(sb + 2 * A_TB + tile * B_TB + n * 64 + swz64(n, h), src);
        }
        CP_COMMIT();
    };

    prefetch(0);

    for (int kc = 0; kc < NKC; kc++) {
        if (kc + 1 < NKC) { prefetch(kc + 1); CP_WAIT(1); }
        else              { CP_WAIT(0); }
        __syncthreads();

        const uint32_t sb = smem + (kc & 1) * STAGE_B;

        #pragma unroll
        for (int s = 0; s < 2; s++) {          // two k16 subs
            const int h = s * 2 + lh;
            uint32_t ah[2][4], al[2][4];
            #pragma unroll
            for (int f = 0; f < 2; f++) {
                int rr = wm * 32 + f * 16 + lrow;
                ldm_x4(ah[f], sb + rr * 64 + swz64(rr, h));
                ldm_x4(al[f], sb + A_TB + rr * 64 + swz64(rr, h));
            }
            uint32_t bh[4][2], bl[4][2];
            #pragma unroll
            for (int jj = 0; jj < 2; jj++) {
                int nn = wn * 32 + jj * 16 + lrow;
                uint32_t r4[4];
                ldm_x4(r4, sb + 2 * A_TB + nn * 64 + swz64(nn, h));
                bh[2 * jj][0] = r4[0]; bh[2 * jj + 1][0] = r4[1];
                bh[2 * jj][1] = r4[2]; bh[2 * jj + 1][1] = r4[3];
                ldm_x4(r4, sb + 2 * A_TB + B_TB + nn * 64 + swz64(nn, h));
                bl[2 * jj][0] = r4[0]; bl[2 * jj + 1][0] = r4[1];
                bl[2 * jj][1] = r4[2]; bl[2 * jj + 1][1] = r4[3];
            }
            #pragma unroll
            for (int mf = 0; mf < 2; mf++)
                #pragma unroll
                for (int nf = 0; nf < 4; nf++) {
                    mma16816(c[mf][nf], ah[mf], bh[nf]);
                    mma16816(c[mf][nf], ah[mf], bl[nf]);
                    mma16816(c[mf][nf], al[mf], bh[nf]);
                }
        }
        __syncthreads();
    }

    const int g  = lane >> 2;
    const int tg = lane & 3;
    #pragma unroll
    for (int nf = 0; nf < 4; nf++) {
        const int col = bc + wn * 32 + nf * 8 + tg * 2;
        const float2 bb = *(const float2*)(b_o + col);
        #pragma unroll
        for (int mf = 0; mf < 2; mf++) {
            const int row0 = br + wm * 32 + mf * 16 + g;
            float2 v0 = make_float2(c[mf][nf][0] + bb.x, c[mf][nf][1] + bb.y);
            float2 v1 = make_float2(c[mf][nf][2] + bb.x, c[mf][nf][3] + bb.y);
            *(float2*)(out + (size_t)row0 * OUT_ + col)       = v0;
            *(float2*)(out + (size_t)(row0 + 8) * OUT_ + col) = v1;
        }
    }
}

// ==================================================================
// Launch
// ==================================================================
extern "C" void kernel_launch(void* const* d_in, const int* in_sizes, int n_in,
                              void* d_out, int out_size)
{
    const float* x    = (const float*)d_in[0];
    const float* mem  = (const float*)d_in[1];
    const float* W_ar = (const float*)d_in[2];
    const float* b_ar = (const float*)d_in[3];
    const float* W_pr = (const float*)d_in[4];
    const float* b_pr = (const float*)d_in[5];
    const float* W_f  = (const float*)d_in[6];
    const float* b_f  = (const float*)d_in[7];
    const float* W_r  = (const float*)d_in[8];
    const float* b_r  = (const float*)d_in[9];
    const float* W_o  = (const float*)d_in[10];
    const float* b_o  = (const float*)d_in[11];

    float* out     = (float*)d_out;
    float* new_mem = out + (size_t)B_ * OUT_;

    const int smemB = (8320 + 4224 + 8448 + 64 + 64 + 66 + 128 + 128 + 9) * 4;
    cudaFuncSetAttribute(mem_kernel, cudaFuncAttributeMaxDynamicSharedMemorySize, smemB);
    cudaFuncSetAttribute(proj_kernel, cudaFuncAttributeMaxDynamicSharedMemorySize, PROJ_SMEM);

    pack_kernel<<<(IN_ * NPAD + 255) / 256, 256>>>(W_ar, W_f, W_r);
    {
        dim3 g(KO / 32, OUT_ / 32);
        conv_B_kernel<<<g, 256>>>(W_o);
    }
    proj_kernel<<<B_ / GROUP, PTH, PROJ_SMEM>>>(x, b_ar, b_f, b_r);
    mem_kernel<<<B_, MTH, smemB>>>(mem, W_pr, b_pr, W_f, W_r, new_mem);
    {
        dim3 g(OUT_ / CTA_N, B_ / CTA_M);   // (16, 8)
        out_gemm_mma<<<g, 256>>>(b_o, out);
    }
}